// round 9
// baseline (speedup 1.0000x reference)
#include <cuda_runtime.h>
#include <math.h>

#define R 1024
#define B 16
#define D 1024
#define K_ACTIVE 20
#define FB_DECAY 0.9f
#define REFR_W 1.0f
#define FB_W 0.5f

#define NBLK ((R * B) / 8)          // 2048 score blocks, 8 rows each
#define NMS_FIRST (NBLK - B)

__device__ int g_count = 0;          // ticket counter (reset by scatter kernel)
__device__ int d_sel[B * K_ACTIVE];  // selected regions per batch

// ordered-uint transform: max(ord(f)) <=> max(f)
__device__ __forceinline__ unsigned f2ord(float f) {
    unsigned u = __float_as_uint(f);
    return u ^ (((int)u >> 31) | 0x80000000u);
}

__device__ __forceinline__ unsigned long long row_max(
    const unsigned long long* __restrict__ my)
{
    const ulonglong2* m2 = (const ulonglong2*)my;   // requires 16B alignment
    unsigned long long a = 0, b = 0;
#pragma unroll
    for (int j = 0; j < 8; j++) {
        ulonglong2 x = m2[2 * j];
        ulonglong2 y = m2[2 * j + 1];
        a = max(a, max(x.x, x.y));
        b = max(b, max(y.x, y.y));
    }
    return max(a, b);
}

// ---------------------------------------------------------------------------
// Kernel 1: score + zero (all blocks) ++ NMS (last 16 blocks to finish).
// ---------------------------------------------------------------------------
__global__ void __launch_bounds__(256)
score_nms_kernel(const float4* __restrict__ H,
                 const float4* __restrict__ M,
                 const float4* __restrict__ w,
                 const float*  __restrict__ theta,
                 const float*  __restrict__ refr,
                 const float*  __restrict__ fb,
                 float* __restrict__ adj_out,     // [B,R]
                 float* __restrict__ hard_out,    // [B,R]
                 float4* __restrict__ hs_out)     // [R,B,D]
{
    const int t    = threadIdx.x;
    const int lane = t & 31;
    const int warp = t >> 5;

    __shared__ __align__(16) float4 s_w[D / 4];
    __shared__ float  s_adj[8];
    __shared__ int    s_tick;

    s_w[t] = w[t];
    __syncthreads();

    // ------------- Phase 1: score + zero (one warp per row) ---------------
    {
        int gw = blockIdx.x * 8 + warp;          // row id rb
        const float4* hrow = H + (size_t)gw * (D / 4);
        const float4* mrow = M + (size_t)gw * (D / 4);
        float4*       orow = hs_out + (size_t)gw * (D / 4);
        const float4 z4 = make_float4(0.f, 0.f, 0.f, 0.f);

        float dot = 0.f, ss = 0.f;
#pragma unroll
        for (int i = 0; i < (D / 4) / 32; i++) {
            int j = i * 32 + lane;
            float4 hv = __ldcs(&hrow[j]);
            float4 mv = __ldcs(&mrow[j]);
            float4 wv = s_w[j];
            dot += hv.x * wv.x + hv.y * wv.y + hv.z * wv.z + hv.w * wv.w;
            ss  += mv.x * mv.x + mv.y * mv.y + mv.z * mv.z + mv.w * mv.w;
            __stcs(&orow[j], z4);
        }
#pragma unroll
        for (int o = 16; o > 0; o >>= 1) {
            dot += __shfl_down_sync(0xffffffffu, dot, o);
            ss  += __shfl_down_sync(0xffffffffu, ss,  o);
        }
        if (lane == 0) {
            int r = gw >> 4, b = gw & 15;
            float fb_new = FB_DECAY * fb[b * R + r] + (1.0f - FB_DECAY) * sqrtf(ss);
            s_adj[warp] = dot - theta[r] - REFR_W * refr[b * R + r] - FB_W * fb_new;
        }
    }
    __syncthreads();

    // ------------- Release: t0 publishes adj, fences ITS stores, tickets ---
    if (t == 0) {
#pragma unroll
        for (int wp = 0; wp < 8; wp++) {
            int gw = blockIdx.x * 8 + wp;
            int r = gw >> 4, b = gw & 15;
            adj_out[b * R + r] = s_adj[wp];
        }
        __threadfence();                       // t0's 8 stores only
        s_tick = atomicAdd(&g_count, 1);
    }
    __syncthreads();
    if (s_tick < NMS_FIRST) return;            // 2032 blocks exit here

    const int b = s_tick - NMS_FIRST;          // this block owns batch b

    if (t == 0) {
        while (*(volatile int*)&g_count < NBLK) __nanosleep(64);
        __threadfence();                       // acquire
    }
    __syncthreads();

    // ------------- Phase 2: NMS for batch b (warp 0) -----------------------
    __shared__ __align__(16) unsigned long long ks[R];
    __shared__ __align__(16) float hm[R];

    for (int i = t; i < R; i += 256) {
        float v = adj_out[b * R + i];
        ks[i] = ((unsigned long long)f2ord(v) << 32) | (unsigned)(~i);
        hm[i] = 0.f;
    }
    __syncthreads();

    if (warp == 0) {
        const unsigned long long* my = ks + lane * 32;  // lane owns grid row
        unsigned long long best = row_max(my);

        for (int it = 0; it < K_ACTIVE; it++) {
            unsigned hi = (unsigned)(best >> 32);
            unsigned mx = __reduce_max_sync(0xffffffffu, hi);
            unsigned lo = (hi == mx) ? (unsigned)best : 0u;
            lo = __reduce_max_sync(0xffffffffu, lo);
            int s = (int)(~lo) & (R - 1);

            int rr = s >> 5, cc = s & 31;
            if (lane == 0) { d_sel[b * K_ACTIVE + it] = s; hm[s] = 1.f; }
            if (lane < 7) {
                int tgt;
                switch (lane) {
                    case 0: tgt = s; break;
                    case 1: tgt = (rr << 5) | ((cc - 1) & 31); break;
                    case 2: tgt = (rr << 5) | ((cc + 1) & 31); break;
                    case 3: tgt = (((rr - 1) & 31) << 5) | cc; break;
                    case 4: tgt = (((rr + 1) & 31) << 5) | cc; break;
                    case 5: tgt = (((rr - 1) & 31) << 5) | ((cc + 1) & 31); break;
                    default: tgt = (((rr + 1) & 31) << 5) | ((cc - 1) & 31); break;
                }
                ks[tgt] = 0ull;
            }
            __syncwarp();
            int dl = (lane - rr) & 31;
            if (dl <= 1 || dl == 31)          // only 3 affected rows re-scan
                best = row_max(my);
        }
    }
    __syncthreads();

    // hard[b,:]
    ((float4*)(hard_out + b * R))[t] = ((const float4*)hm)[t];
}

// ---------------------------------------------------------------------------
// Kernel 2: scatter-copy the 320 active rows (Hs[r,b,:] = H[r,b,:]) and
// reset the ticket counter for the next graph replay. Kernel boundary
// orders this after ALL of kernel 1's zero-stores (no WAW race).
// (ste = hard + sigma - stopgrad(sigma): numerically hard, err < 6e-8.)
// ---------------------------------------------------------------------------
__global__ void __launch_bounds__(256)
scatter_kernel(const float4* __restrict__ H,
               float4* __restrict__ out)
{
    if (blockIdx.x == 0 && threadIdx.x == 0) g_count = 0;   // replay reset
    int bi   = blockIdx.x;              // 0 .. B*K_ACTIVE-1
    int b    = bi / K_ACTIVE;
    int slot = bi - b * K_ACTIVE;
    int r    = d_sel[b * K_ACTIVE + slot];
    size_t row = (size_t)(r * B + b) * (D / 4);
    out[row + threadIdx.x] = H[row + threadIdx.x];
}

// ---------------------------------------------------------------------------
extern "C" void kernel_launch(void* const* d_in, const int* in_sizes, int n_in,
                              void* d_out, int out_size)
{
    const float* H     = (const float*)d_in[0];   // [R,B,D]
    const float* M     = (const float*)d_in[1];   // [R,B,D]
    const float* w     = (const float*)d_in[2];   // [D]
    const float* theta = (const float*)d_in[3];   // [R]
    const float* refr  = (const float*)d_in[4];   // [B,R]
    const float* fb    = (const float*)d_in[5];   // [B,R]
    // d_in[6] = neighbor_indices: fixed 32x32 toroidal hex grid, computed
    // arithmetically in-kernel.

    float* out  = (float*)d_out;
    float* Hs   = out;                              // [R,B,D]
    float* hard = out + (size_t)R * B * D;          // [B,R]
    float* adj  = hard + (size_t)B * R;             // [B,R]

    score_nms_kernel<<<NBLK, 256>>>((const float4*)H, (const float4*)M,
                                    (const float4*)w, theta, refr, fb,
                                    adj, hard, (float4*)Hs);
    scatter_kernel<<<B * K_ACTIVE, 256>>>((const float4*)H, (float4*)Hs);
}

// round 10
// speedup vs baseline: 1.3530x; 1.3530x over previous
#include <cuda_runtime.h>
#include <math.h>

#define R 1024
#define B 16
#define D 1024
#define K_ACTIVE 20
#define FB_DECAY 0.9f
#define REFR_W 1.0f
#define FB_W 0.5f

// ---------------------------------------------------------------------------
// Kernel 1: fused per-(r,b) row reductions + zero-fill of the Hs output row.
//   adj[b,r] = dot(H,w) - theta[r] - refr[b,r] - 0.5*(0.9*fb + 0.1*||msg||)
//   Hs[r,b,:] = 0   (active rows overwritten by kernel 2's scatter)
// (proven: 30.6us, 68% DRAM)
// ---------------------------------------------------------------------------
__global__ void __launch_bounds__(256)
score_zero_kernel(const float4* __restrict__ H,
                  const float4* __restrict__ M,
                  const float4* __restrict__ w,
                  const float*  __restrict__ theta,
                  const float*  __restrict__ refr,
                  const float*  __restrict__ fb,
                  float* __restrict__ adj_out,
                  float4* __restrict__ hs_out)
{
    __shared__ __align__(16) float4 s_w[D / 4];
    s_w[threadIdx.x] = w[threadIdx.x];
    __syncthreads();

    int gw   = blockIdx.x * 8 + (threadIdx.x >> 5);   // row id rb
    int lane = threadIdx.x & 31;
    int r = gw >> 4;
    int b = gw & 15;

    const float4* hrow = H + (size_t)gw * (D / 4);
    const float4* mrow = M + (size_t)gw * (D / 4);
    float4*       orow = hs_out + (size_t)gw * (D / 4);
    const float4 z4 = make_float4(0.f, 0.f, 0.f, 0.f);

    float dot = 0.f, ss = 0.f;
#pragma unroll
    for (int i = 0; i < (D / 4) / 32; i++) {
        int j = i * 32 + lane;
        float4 hv = __ldcs(&hrow[j]);
        float4 mv = __ldcs(&mrow[j]);
        float4 wv = s_w[j];
        dot += hv.x * wv.x + hv.y * wv.y + hv.z * wv.z + hv.w * wv.w;
        ss  += mv.x * mv.x + mv.y * mv.y + mv.z * mv.z + mv.w * mv.w;
        __stcs(&orow[j], z4);
    }
#pragma unroll
    for (int o = 16; o > 0; o >>= 1) {
        dot += __shfl_down_sync(0xffffffffu, dot, o);
        ss  += __shfl_down_sync(0xffffffffu, ss,  o);
    }
    if (lane == 0) {
        int br = b * R + r;
        float fb_new = FB_DECAY * fb[br] + (1.0f - FB_DECAY) * sqrtf(ss);
        adj_out[br] = dot - theta[r] - REFR_W * refr[br] - FB_W * fb_new;
    }
}

// ordered-uint transform: max(ord(f)) <=> max(f)
__device__ __forceinline__ unsigned f2ord(float f) {
    unsigned u = __float_as_uint(f);
    return u ^ (((int)u >> 31) | 0x80000000u);
}

// ---------------------------------------------------------------------------
// Kernel 2: greedy hex NMS via parallel lexicographic-MIS relaxation,
// + hard write + scatter of active rows. One block (1024 threads) per batch.
//
//   key(v) = (ord(adj) << 32) | ~v    (total order == JAX stable argsort)
//   v SELECTED  iff all higher-key neighbors REJECTED
//   v REJECTED  iff some higher-key neighbor SELECTED
//   greedy-with-limit-k == the k highest-keyed members of this MIS.
// Races within a round are benign: statuses are monotone (0 -> 1|2, final)
// and any decided value is sound, so fresher reads only accelerate.
// ---------------------------------------------------------------------------
__global__ void __launch_bounds__(1024)
nms_scatter_kernel(const float* __restrict__ adj,
                   const float4* __restrict__ H,
                   float* __restrict__ hard,
                   float4* __restrict__ hs_out)
{
    const int b = blockIdx.x;
    const int t = threadIdx.x;          // == region index

    __shared__ __align__(16) unsigned long long key[R];
    __shared__ int status[R];           // 0 unknown, 1 selected, 2 rejected
    __shared__ int selList[512];        // MIS <= ~342 members on hex torus
    __shared__ int hardFlag[R];
    __shared__ int selTop[K_ACTIVE];
    __shared__ int scnt;

    unsigned long long my =
        ((unsigned long long)f2ord(adj[b * R + t]) << 32) | (unsigned)(~t);
    key[t] = my;
    status[t] = 0;
    hardFlag[t] = 0;
    if (t == 0) scnt = 0;
    if (t < K_ACTIVE) selTop[t] = 0;
    __syncthreads();

    // 6 hex neighbors on the 32x32 torus; precompute which are higher-key
    int rr = t >> 5, cc = t & 31;
    int nb[6] = { (rr << 5) | ((cc - 1) & 31),
                  (rr << 5) | ((cc + 1) & 31),
                  (((rr - 1) & 31) << 5) | cc,
                  (((rr + 1) & 31) << 5) | cc,
                  (((rr - 1) & 31) << 5) | ((cc + 1) & 31),
                  (((rr + 1) & 31) << 5) | ((cc - 1) & 31) };
    bool hi[6];
#pragma unroll
    for (int j = 0; j < 6; j++) hi[j] = key[nb[j]] > my;

    int st = 0;
    for (int round = 0; round < 64; round++) {
        if (st == 0) {
            bool anySel = false, allRej = true;
#pragma unroll
            for (int j = 0; j < 6; j++) {
                if (hi[j]) {
                    int s2 = status[nb[j]];
                    anySel |= (s2 == 1);
                    allRej &= (s2 == 2);
                }
            }
            if (anySel)      st = 2;
            else if (allRej) st = 1;
            if (st) status[t] = st;
        }
        if (__syncthreads_count(st == 0) == 0) break;
    }

    // collect MIS members
    if (st == 1) {
        int p = atomicAdd(&scnt, 1);
        if (p < 512) selList[p] = t;
    }
    __syncthreads();
    int S = min(scnt, 512);

    // rank: member is active iff fewer than K higher-keyed members exist;
    // its rank c is also its greedy selection order.
    if (t < S) {
        int idx = selList[t];
        unsigned long long kk = key[idx];
        int c = 0;
#pragma unroll 8
        for (int j = 0; j < S; j++)
            c += (key[selList[j]] > kk);
        if (c < K_ACTIVE) { hardFlag[idx] = 1; selTop[c] = idx; }
    }
    __syncthreads();

    // hard[b,:]
    hard[b * R + t] = (float)hardFlag[t];

    // scatter the 20 active rows: Hs[r,b,:] = H[r,b,:]
    // (ste = hard + sigma - stopgrad(sigma): numerically hard, err < 6e-8)
    // 20 rows x 256 float4 = 5120 chunks over 1024 threads -> 5 each, all
    // independent (full MLP).
#pragma unroll
    for (int e = 0; e < 5; e++) {
        int g    = t + e * 1024;        // 0..5119
        int srow = g >> 8;              // 0..19
        int off  = g & 255;
        int r    = selTop[srow];
        size_t row = (size_t)(r * B + b) * (D / 4);
        hs_out[row + off] = H[row + off];
    }
}

// ---------------------------------------------------------------------------
extern "C" void kernel_launch(void* const* d_in, const int* in_sizes, int n_in,
                              void* d_out, int out_size)
{
    const float* H     = (const float*)d_in[0];   // [R,B,D]
    const float* M     = (const float*)d_in[1];   // [R,B,D]
    const float* w     = (const float*)d_in[2];   // [D]
    const float* theta = (const float*)d_in[3];   // [R]
    const float* refr  = (const float*)d_in[4];   // [B,R]
    const float* fb    = (const float*)d_in[5];   // [B,R]
    // d_in[6] = neighbor_indices: fixed 32x32 toroidal hex grid, computed
    // arithmetically in-kernel.

    float* out  = (float*)d_out;
    float* Hs   = out;                              // [R,B,D]
    float* hard = out + (size_t)R * B * D;          // [B,R]
    float* adj  = hard + (size_t)B * R;             // [B,R]

    score_zero_kernel<<<(R * B) / 8, 256>>>((const float4*)H, (const float4*)M,
                                            (const float4*)w, theta, refr, fb,
                                            adj, (float4*)Hs);
    nms_scatter_kernel<<<B, 1024>>>(adj, (const float4*)H, hard, (float4*)Hs);
}